// round 5
// baseline (speedup 1.0000x reference)
#include <cuda_runtime.h>
#include <math.h>
#include <stdint.h>

#define BSZ    2
#define SEQ    2048
#define DMODEL 2048
#define NHEADS 16
#define HDIM   128
#define BH     (BSZ*NHEADS)
#define MROWS  (BSZ*SEQ)

// ---- scratch ----
__device__ float g_q[BH*SEQ*HDIM];
__device__ float g_k[BH*SEQ*HDIM];
__device__ float g_v[BH*SEQ*HDIM];
__device__ float g_attn[MROWS*DMODEL];
__device__ float g_cos[SEQ*64];
__device__ float g_sin[SEQ*64];

__device__ __forceinline__ float to_tf32(float x) {
    float y;
    asm("cvt.rna.tf32.f32 %0, %1;" : "=f"(y) : "f"(x));
    return y;
}
__device__ __forceinline__ uint32_t tf32_bits(float x) {
    return __float_as_uint(to_tf32(x));
}
__device__ __forceinline__ void mma_tf32(float* c, const uint32_t* a, const uint32_t* b) {
    asm volatile(
        "mma.sync.aligned.m16n8k8.row.col.f32.tf32.tf32.f32 "
        "{%0,%1,%2,%3}, {%4,%5,%6,%7}, {%8,%9}, {%0,%1,%2,%3};"
        : "+f"(c[0]), "+f"(c[1]), "+f"(c[2]), "+f"(c[3])
        : "r"(a[0]), "r"(a[1]), "r"(a[2]), "r"(a[3]), "r"(b[0]), "r"(b[1]));
}
__device__ __forceinline__ float4 tf32x4(float4 v) {
    v.x = to_tf32(v.x); v.y = to_tf32(v.y); v.z = to_tf32(v.z); v.w = to_tf32(v.w);
    return v;
}
__device__ __forceinline__ uint32_t smem_u32(const void* p) {
    uint32_t a;
    asm("{ .reg .u64 t; cvta.to.shared.u64 t, %1; cvt.u32.u64 %0, t; }" : "=r"(a) : "l"(p));
    return a;
}
__device__ __forceinline__ void cp16(uint32_t dst, const void* src) {
    asm volatile("cp.async.cg.shared.global [%0], [%1], 16;" :: "r"(dst), "l"(src));
}
__device__ __forceinline__ void cp_commit() {
    asm volatile("cp.async.commit_group;" ::: "memory");
}
__device__ __forceinline__ void cp_wait1() {
    asm volatile("cp.async.wait_group 1;" ::: "memory");
}

// =================== RoPE ===================
__global__ void rope_cache_kernel() {
    int idx = blockIdx.x * blockDim.x + threadIdx.x;
    if (idx >= SEQ * 64) return;
    int pos = idx >> 6, j = idx & 63;
    double e    = (double)(2 * j) / 128.0;
    double invf = pow(10000.0, -e);
    double ang  = (double)pos * invf;
    g_cos[idx] = (float)cos(ang);
    g_sin[idx] = (float)sin(ang);
}
__global__ void rope_apply_kernel() {
    int idx = blockIdx.x * blockDim.x + threadIdx.x;
    if (idx >= BH * SEQ * 64) return;
    int j = idx & 63, row = idx >> 6, s = row & (SEQ - 1);
    float c = g_cos[s * 64 + j], sn = g_sin[s * 64 + j];
    float* qp = g_q + (size_t)row * HDIM;
    float* kp = g_k + (size_t)row * HDIM;
    float q1 = qp[j], q2 = qp[j + 64];
    qp[j] = q1 * c - q2 * sn;  qp[j + 64] = q2 * c + q1 * sn;
    float k1 = kp[j], k2 = kp[j + 64];
    kp[j] = k1 * c - k2 * sn;  kp[j + 64] = k2 * c + k1 * sn;
}

// =================== TF32 GEMM: 4 warps, 64x64 warp tile, cp.async 3-stage ===================
// C[m,n] = sum_k A[m,k]*B[n,k]. 128x128 CTA tile, K stage 16.
// A e-plane: slot = (mt*2+kb)*AT + e*AE + lane  (mt 0..7)
// B e-plane: slot = (nt*2+kb)*BT + e*BE + lane  (nt 0..15)
#define GEMM_K  DMODEL
#define KSTAGES (GEMM_K / 16)    // 128
#define AE 36
#define AT 144
#define BE 40
#define BT 80
#define A_STAGE (16*AT)          // 2304 words
#define B_STAGE (32*BT)          // 2560 words
#define NSTG 3
#define STAGE_WORDS (A_STAGE + B_STAGE)            // 4864
#define GEMM_SMEM_BYTES (NSTG * STAGE_WORDS * 4)   // 58368

__global__ __launch_bounds__(128, 2)
void tf32_gemm(const float* __restrict__ A, const float* __restrict__ B,
               float* __restrict__ C, int mode)
{
    extern __shared__ float smem[];
    const int tid  = threadIdx.x;
    const int wid  = tid >> 5;
    const int lane = tid & 31;
    const int bm = blockIdx.y * 128;
    const int bn = blockIdx.x * 128;
    const int wm = wid >> 1;          // 0..1
    const int wn = wid & 1;           // 0..1
    const uint32_t smb = smem_u32(smem);

    // fill mapping: 4 x 16B chunks per operand per thread per stage
    uint32_t aS[4], bS[4];
    const char* aG[4];
    const char* bG[4];
#pragma unroll
    for (int i = 0; i < 4; i++) {
        int f = i * 128 + tid;        // 0..511
        int row = f >> 2, c4 = f & 3;
        int kb = c4 >> 1, kh = c4 & 1;
        int g = row & 7, hi = (row >> 3) & 1;
        int mt = row >> 4, nt = row >> 3;
        aS[i] = smb + (((mt * 2 + kb) * AT + (hi + 2 * kh) * AE + g * 4) << 2);
        bS[i] = smb + ((A_STAGE + (nt * 2 + kb) * BT + kh * BE + g * 4) << 2);
        aG[i] = (const char*)(A + (size_t)(bm + row) * GEMM_K + c4 * 4);
        bG[i] = (const char*)(B + (size_t)(bn + row) * GEMM_K + c4 * 4);
    }

#define FILL(ks_) do {                                                   \
        uint32_t off_ = (uint32_t)(((ks_) % NSTG) * (STAGE_WORDS * 4));  \
        size_t go_ = (size_t)(ks_) * 64;                                 \
        _Pragma("unroll")                                                \
        for (int i_ = 0; i_ < 4; i_++) {                                 \
            cp16(aS[i_] + off_, aG[i_] + go_);                           \
            cp16(bS[i_] + off_, bG[i_] + go_);                           \
        }                                                                \
    } while (0)

    FILL(0); cp_commit();
    FILL(1); cp_commit();

    float acc[4][8][4];
#pragma unroll
    for (int mt = 0; mt < 4; mt++)
#pragma unroll
        for (int nt = 0; nt < 8; nt++)
#pragma unroll
            for (int e = 0; e < 4; e++) acc[mt][nt][e] = 0.f;

#pragma unroll 1
    for (int ks = 0; ks < KSTAGES; ks++) {
        cp_wait1();
        __syncthreads();
        if (ks + 2 < KSTAGES) FILL(ks + 2);
        cp_commit();

        const float* As_ = smem + (ks % NSTG) * STAGE_WORDS;
        const float* Bs_ = As_ + A_STAGE;
#pragma unroll
        for (int kb = 0; kb < 2; kb++) {
            uint32_t a[4][4], b[8][2];
#pragma unroll
            for (int mt = 0; mt < 4; mt++)
#pragma unroll
                for (int e = 0; e < 4; e++)
                    a[mt][e] = tf32_bits(As_[((wm * 4 + mt) * 2 + kb) * AT + e * AE + lane]);
#pragma unroll
            for (int nt = 0; nt < 8; nt++)
#pragma unroll
                for (int e = 0; e < 2; e++)
                    b[nt][e] = tf32_bits(Bs_[((wn * 8 + nt) * 2 + kb) * BT + e * BE + lane]);
#pragma unroll
            for (int mt = 0; mt < 4; mt++)
#pragma unroll
                for (int nt = 0; nt < 8; nt++)
                    mma_tf32(acc[mt][nt], a[mt], b[nt]);
        }
    }
#undef FILL

    // epilogue
    const int g = lane >> 2, tig = lane & 3;
#pragma unroll
    for (int mt = 0; mt < 4; mt++) {
#pragma unroll
        for (int nt = 0; nt < 8; nt++) {
            int row = bm + wm * 64 + mt * 16 + g;
            int col = bn + wn * 64 + nt * 8 + tig * 2;
            float* c0;
            size_t rstride;
            if (mode == 0) {
                c0 = C + (size_t)row * DMODEL + col;
                rstride = DMODEL;
            } else {
                int b = row >> 11, s = row & (SEQ - 1);
                int h = col >> 7, hd = col & 127;
                c0 = C + (((size_t)(b * NHEADS + h)) * SEQ + s) * HDIM + hd;
                rstride = HDIM;
            }
            *(float2*)c0 = make_float2(acc[mt][nt][0], acc[mt][nt][1]);
            *(float2*)(c0 + 8 * rstride) = make_float2(acc[mt][nt][2], acc[mt][nt][3]);
        }
    }
}

// =================== Flash attention (causal, tf32 mma) ===================
#define QTS 132
#define KE  36
#define KTS 72
#define VTS 580
#define OFF_KF 8448
#define OFF_VF 17664
#define OFF_PS 26944
#define OFF_RM 31296
#define FLASH_SMEM_BYTES ((OFF_RM + 3*64) * 4)   // 125952 B

__global__ __launch_bounds__(256)
void flash_fwd(const float* __restrict__ Qg, const float* __restrict__ Kg,
               const float* __restrict__ Vg, float* __restrict__ Og)
{
    extern __shared__ float smf[];
    float* Qf = smf;
    float* Kf = smf + OFF_KF;
    float* Vf = smf + OFF_VF;
    float* Ps = smf + OFF_PS;
    float* rm = smf + OFF_RM;
    float* rl = rm + 64;
    float* ra = rl + 64;

    const int tid  = threadIdx.x;
    const int wid  = tid >> 5;
    const int lane = tid & 31;
    const int g4 = lane >> 2, tig = lane & 3;
    const int wm = wid >> 2;
    const int wn = wid & 3;
    const int bx = blockIdx.x;
    const int bh = blockIdx.y;
    const int m0 = bx * 64;
    const size_t base = (size_t)bh * SEQ * HDIM;
    const float scale = 0.08838834764831845f;

#pragma unroll
    for (int i = 0; i < 8; i++) {
        int row = i * 8 + wid;
        float4 v = *(const float4*)(Qg + base + (size_t)(m0 + row) * HDIM + lane * 4);
        v = tf32x4(v);
        int mt = row >> 4, g = row & 7, hi = (row >> 3) & 1;
        int kt = lane >> 1, kh = lane & 1;
        int w = (mt * 16 + kt) * QTS + 16 * g + (hi + 2 * kh);
        Qf[w + 0] = v.x; Qf[w + 4] = v.y; Qf[w + 8] = v.z; Qf[w + 12] = v.w;
    }
    if (tid < 64) { rm[tid] = -1e30f; rl[tid] = 0.f; }

    float o[2][4][4];
#pragma unroll
    for (int mt = 0; mt < 2; mt++)
#pragma unroll
        for (int nt = 0; nt < 4; nt++)
#pragma unroll
            for (int e = 0; e < 4; e++) o[mt][nt][e] = 0.f;

    const int ntiles = bx + 1;
    for (int t = 0; t < ntiles; t++) {
        const int n0 = t * 64;
        __syncthreads();

#pragma unroll
        for (int i = 0; i < 8; i++) {
            int row = i * 8 + wid;
            const float* src = (const float*)(Kg + base + (size_t)(n0 + row) * HDIM) + lane * 4;
            float4 kv = tf32x4(*(const float4*)src);
            {
                int g = row & 7, nt = row >> 3;
                int kt = lane >> 1, kh = lane & 1;
                *(float4*)&Kf[(nt * 16 + kt) * KTS + kh * KE + g * 4] = kv;
            }
            float4 vv = tf32x4(*(const float4*)(Vg + base + (size_t)(n0 + row) * HDIM + lane * 4));
            {
                int ktv = row >> 3, ev = (row >> 2) & 1, gk = row & 3;
                float vj[4] = {vv.x, vv.y, vv.z, vv.w};
#pragma unroll
                for (int j = 0; j < 4; j++) {
                    int n = 4 * lane + j;
                    Vf[(n >> 3) * VTS + ktv * KTS + ev * KE + ((n & 7) << 2) + gk] = vj[j];
                }
            }
        }
        __syncthreads();

        float s[2][2][4];
#pragma unroll
        for (int mt = 0; mt < 2; mt++)
#pragma unroll
            for (int nt = 0; nt < 2; nt++)
#pragma unroll
                for (int e = 0; e < 4; e++) s[mt][nt][e] = 0.f;

#pragma unroll
        for (int kt = 0; kt < 16; kt++) {
            uint32_t a[2][4], b[2][2];
#pragma unroll
            for (int mt = 0; mt < 2; mt++)
                *(uint4*)a[mt] = *(const uint4*)&Qf[((wm * 2 + mt) * 16 + kt) * QTS + lane * 4];
#pragma unroll
            for (int nt = 0; nt < 2; nt++)
#pragma unroll
                for (int e = 0; e < 2; e++)
                    b[nt][e] = __float_as_uint(Kf[((wn * 2 + nt) * 16 + kt) * KTS + e * KE + lane]);
#pragma unroll
            for (int mt = 0; mt < 2; mt++)
#pragma unroll
                for (int nt = 0; nt < 2; nt++)
                    mma_tf32(s[mt][nt], a[mt], b[nt]);
        }

        const bool diag = (t == bx);
#pragma unroll
        for (int mt = 0; mt < 2; mt++) {
#pragma unroll
            for (int nt = 0; nt < 2; nt++) {
                int r0 = wm * 32 + mt * 16 + g4;
                int c0 = wn * 16 + nt * 8 + 2 * tig;
#pragma unroll
                for (int h = 0; h < 2; h++) {
                    int rr = r0 + h * 8;
                    float v0 = s[mt][nt][2 * h + 0] * scale;
                    float v1 = s[mt][nt][2 * h + 1] * scale;
                    if (diag) {
                        int grow = m0 + rr;
                        if (n0 + c0     > grow) v0 = -1e30f;
                        if (n0 + c0 + 1 > grow) v1 = -1e30f;
                    }
                    *(float2*)&Ps[rr * 68 + c0] = make_float2(v0, v1);
                }
            }
        }
        __syncthreads();

        {
            int row = tid >> 2, q = tid & 3;
            float* pr = Ps + row * 68 + q * 16;
            float mo = rm[row];
            float mx = mo;
#pragma unroll
            for (int c = 0; c < 16; c++) mx = fmaxf(mx, pr[c]);
            mx = fmaxf(mx, __shfl_xor_sync(0xFFFFFFFFu, mx, 1));
            mx = fmaxf(mx, __shfl_xor_sync(0xFFFFFFFFu, mx, 2));
            float l = 0.f;
#pragma unroll
            for (int c = 0; c < 16; c++) {
                float p = __expf(pr[c] - mx);
                l += p;
                pr[c] = to_tf32(p);
            }
            l += __shfl_xor_sync(0xFFFFFFFFu, l, 1);
            l += __shfl_xor_sync(0xFFFFFFFFu, l, 2);
            if (q == 0) {
                float alpha = __expf(mo - mx);
                rl[row] = rl[row] * alpha + l;
                rm[row] = mx;
                ra[row] = alpha;
            }
        }
        __syncthreads();

        {
            int rb0 = wm * 32 + g4;
            float al[2][2];
#pragma unroll
            for (int mt = 0; mt < 2; mt++) {
                al[mt][0] = ra[rb0 + mt * 16];
                al[mt][1] = ra[rb0 + mt * 16 + 8];
            }
#pragma unroll
            for (int mt = 0; mt < 2; mt++)
#pragma unroll
                for (int nt = 0; nt < 4; nt++) {
                    o[mt][nt][0] *= al[mt][0]; o[mt][nt][1] *= al[mt][0];
                    o[mt][nt][2] *= al[mt][1]; o[mt][nt][3] *= al[mt][1];
                }
#pragma unroll
            for (int kt = 0; kt < 8; kt++) {
                uint32_t a[2][4], b[4][2];
#pragma unroll
                for (int mt = 0; mt < 2; mt++) {
                    int rb = wm * 32 + mt * 16;
                    a[mt][0] = __float_as_uint(Ps[(rb + g4) * 68 + kt * 8 + tig]);
                    a[mt][1] = __float_as_uint(Ps[(rb + 8 + g4) * 68 + kt * 8 + tig]);
                    a[mt][2] = __float_as_uint(Ps[(rb + g4) * 68 + kt * 8 + tig + 4]);
                    a[mt][3] = __float_as_uint(Ps[(rb + 8 + g4) * 68 + kt * 8 + tig + 4]);
                }
#pragma unroll
                for (int nt = 0; nt < 4; nt++)
#pragma unroll
                    for (int e = 0; e < 2; e++)
                        b[nt][e] = __float_as_uint(Vf[(wn * 4 + nt) * VTS + kt * KTS + e * KE + lane]);
#pragma unroll
                for (int mt = 0; mt < 2; mt++)
#pragma unroll
                    for (int nt = 0; nt < 4; nt++)
                        mma_tf32(o[mt][nt], a[mt], b[nt]);
            }
        }
    }

    const int b = bh >> 4, h = bh & 15;
#pragma unroll
    for (int mt = 0; mt < 2; mt++) {
        int rloc0 = wm * 32 + mt * 16 + g4;
#pragma unroll
        for (int hh = 0; hh < 2; hh++) {
            int rloc = rloc0 + hh * 8;
            float inv = 1.f / rl[rloc];
            int srow = m0 + rloc;
            float* op = Og + ((size_t)(b * SEQ + srow)) * DMODEL + h * HDIM;
#pragma unroll
            for (int nt = 0; nt < 4; nt++) {
                int col = wn * 32 + nt * 8 + 2 * tig;
                *(float2*)(op + col) = make_float2(o[mt][nt][2 * hh] * inv,
                                                   o[mt][nt][2 * hh + 1] * inv);
            }
        }
    }
}

// =================== launch ===================
extern "C" void kernel_launch(void* const* d_in, const int* in_sizes, int n_in,
                              void* d_out, int out_size)
{
    (void)in_sizes; (void)n_in; (void)out_size;
    const float* hidden = (const float*)d_in[0];
    const float* Wq = (const float*)d_in[3];
    const float* Wk = (const float*)d_in[4];
    const float* Wv = (const float*)d_in[5];
    const float* Wo = (const float*)d_in[6];
    float* out = (float*)d_out;

    float *q, *k, *v, *attn;
    cudaGetSymbolAddress((void**)&q,    g_q);
    cudaGetSymbolAddress((void**)&k,    g_k);
    cudaGetSymbolAddress((void**)&v,    g_v);
    cudaGetSymbolAddress((void**)&attn, g_attn);

    cudaFuncSetAttribute(flash_fwd, cudaFuncAttributeMaxDynamicSharedMemorySize,
                         FLASH_SMEM_BYTES);
    cudaFuncSetAttribute(tf32_gemm, cudaFuncAttributeMaxDynamicSharedMemorySize,
                         GEMM_SMEM_BYTES);

    rope_cache_kernel<<<(SEQ * 64 + 255) / 256, 256>>>();

    dim3 ggrid(DMODEL / 128, MROWS / 128);   // (16, 32)
    tf32_gemm<<<ggrid, 128, GEMM_SMEM_BYTES>>>(hidden, Wq, q, 1);
    tf32_gemm<<<ggrid, 128, GEMM_SMEM_BYTES>>>(hidden, Wk, k, 1);
    tf32_gemm<<<ggrid, 128, GEMM_SMEM_BYTES>>>(hidden, Wv, v, 1);

    rope_apply_kernel<<<(BH * SEQ * 64 + 255) / 256, 256>>>();

    flash_fwd<<<dim3(SEQ / 64, BH), 256, FLASH_SMEM_BYTES>>>(q, k, v, attn);

    tf32_gemm<<<ggrid, 128, GEMM_SMEM_BYTES>>>(attn, Wo, out, 0);
}

// round 6
// speedup vs baseline: 1.2047x; 1.2047x over previous
#include <cuda_runtime.h>
#include <math.h>
#include <stdint.h>

#define BSZ    2
#define SEQ    2048
#define DMODEL 2048
#define NHEADS 16
#define HDIM   128
#define BH     (BSZ*NHEADS)
#define MROWS  (BSZ*SEQ)

// ---- scratch ----
__device__ float g_q[BH*SEQ*HDIM];
__device__ float g_k[BH*SEQ*HDIM];
__device__ float g_v[BH*SEQ*HDIM];
__device__ float g_attn[MROWS*DMODEL];
__device__ float g_cos[SEQ*64];
__device__ float g_sin[SEQ*64];

__device__ __forceinline__ float to_tf32(float x) {
    float y;
    asm("cvt.rna.tf32.f32 %0, %1;" : "=f"(y) : "f"(x));
    return y;
}
__device__ __forceinline__ void mma_tf32(float* c, const uint32_t* a, const uint32_t* b) {
    asm volatile(
        "mma.sync.aligned.m16n8k8.row.col.f32.tf32.tf32.f32 "
        "{%0,%1,%2,%3}, {%4,%5,%6,%7}, {%8,%9}, {%0,%1,%2,%3};"
        : "+f"(c[0]), "+f"(c[1]), "+f"(c[2]), "+f"(c[3])
        : "r"(a[0]), "r"(a[1]), "r"(a[2]), "r"(a[3]), "r"(b[0]), "r"(b[1]));
}
__device__ __forceinline__ float4 tf32x4(float4 v) {
    v.x = to_tf32(v.x); v.y = to_tf32(v.y); v.z = to_tf32(v.z); v.w = to_tf32(v.w);
    return v;
}

// =================== RoPE ===================
__global__ void rope_cache_kernel() {
    int idx = blockIdx.x * blockDim.x + threadIdx.x;
    if (idx >= SEQ * 64) return;
    int pos = idx >> 6, j = idx & 63;
    double e    = (double)(2 * j) / 128.0;
    double invf = pow(10000.0, -e);
    double ang  = (double)pos * invf;
    g_cos[idx] = (float)cos(ang);
    g_sin[idx] = (float)sin(ang);
}
__global__ void rope_apply_kernel() {
    int idx = blockIdx.x * blockDim.x + threadIdx.x;
    if (idx >= BH * SEQ * 64) return;
    int j = idx & 63, row = idx >> 6, s = row & (SEQ - 1);
    float c = g_cos[s * 64 + j], sn = g_sin[s * 64 + j];
    float* qp = g_q + (size_t)row * HDIM;
    float* kp = g_k + (size_t)row * HDIM;
    float q1 = qp[j], q2 = qp[j + 64];
    qp[j] = q1 * c - q2 * sn;  qp[j + 64] = q2 * c + q1 * sn;
    float k1 = kp[j], k2 = kp[j + 64];
    kp[j] = k1 * c - k2 * sn;  kp[j + 64] = k2 * c + k1 * sn;
}

// =================== TF32 GEMM (R3 design: e-plane, double-buffered, 8 warps) ===================
// C[m,n] = sum_k A[m,k]*B[n,k]. blockIdx.z selects (B,C) for fused QKV.
// mode 0: row-major C    mode 1: scatter to [b,h,s,hd]
#define GEMM_K  DMODEL
#define KSTAGES (GEMM_K / 16)    // 128
#define AE 36
#define AT 144
#define BE 40
#define BT 80
#define A_STAGE (16*AT)
#define B_STAGE (32*BT)

__global__ __launch_bounds__(256, 2)
void tf32_gemm(const float* __restrict__ A,
               const float* __restrict__ B0, const float* __restrict__ B1,
               const float* __restrict__ B2,
               float* __restrict__ C0, float* __restrict__ C1, float* __restrict__ C2,
               int mode)
{
    __shared__ float As[2][A_STAGE];
    __shared__ float Bs[2][B_STAGE];

    const int z = blockIdx.z;
    const float* B = (z == 0) ? B0 : (z == 1) ? B1 : B2;
    float* C       = (z == 0) ? C0 : (z == 1) ? C1 : C2;

    const int tid  = threadIdx.x;
    const int wid  = tid >> 5;
    const int lane = tid & 31;
    const int bm = blockIdx.y * 128;
    const int bn = blockIdx.x * 128;
    const int wm = wid >> 2;
    const int wn = wid & 3;

    int aWord[2], bWord[2];
    const float4* Ap[2];
    const float4* Bp[2];
#pragma unroll
    for (int i = 0; i < 2; i++) {
        int f = i * 256 + tid;
        int row = f >> 2, c4 = f & 3;
        int kb = c4 >> 1, kh = c4 & 1;
        int g = row & 7, hi = (row >> 3) & 1;
        int mt = row >> 4, nt = row >> 3;
        aWord[i] = (mt * 2 + kb) * AT + (hi + 2 * kh) * AE + g * 4;
        bWord[i] = (nt * 2 + kb) * BT + kh * BE + g * 4;
        Ap[i] = (const float4*)(A + (size_t)(bm + row) * GEMM_K) + c4;
        Bp[i] = (const float4*)(B + (size_t)(bn + row) * GEMM_K) + c4;
    }

    float acc[4][4][4];
#pragma unroll
    for (int mt = 0; mt < 4; mt++)
#pragma unroll
        for (int nt = 0; nt < 4; nt++)
#pragma unroll
            for (int e = 0; e < 4; e++) acc[mt][nt][e] = 0.f;

    float4 pa[2], pb[2];
#pragma unroll
    for (int i = 0; i < 2; i++) { pa[i] = Ap[i][0]; pb[i] = Bp[i][0]; }
#pragma unroll
    for (int i = 0; i < 2; i++) {
        *(float4*)&As[0][aWord[i]] = tf32x4(pa[i]);
        *(float4*)&Bs[0][bWord[i]] = tf32x4(pb[i]);
    }
#pragma unroll
    for (int i = 0; i < 2; i++) { pa[i] = Ap[i][4]; pb[i] = Bp[i][4]; }
    __syncthreads();

    const int aT0 = (wm * 4) * 2 * AT;
    const int bT0 = (wn * 4) * 2 * BT;

#pragma unroll 1
    for (int ks = 0; ks < KSTAGES; ks++) {
        const int buf = ks & 1;
        if (ks + 1 < KSTAGES) {
#pragma unroll
            for (int i = 0; i < 2; i++) {
                *(float4*)&As[buf ^ 1][aWord[i]] = tf32x4(pa[i]);
                *(float4*)&Bs[buf ^ 1][bWord[i]] = tf32x4(pb[i]);
            }
        }
#pragma unroll
        for (int kb = 0; kb < 2; kb++) {
            uint32_t a[4][4], b[4][2];
#pragma unroll
            for (int mt = 0; mt < 4; mt++)
#pragma unroll
                for (int e = 0; e < 4; e++)
                    a[mt][e] = __float_as_uint(As[buf][aT0 + (mt * 2 + kb) * AT + e * AE + lane]);
#pragma unroll
            for (int nt = 0; nt < 4; nt++)
#pragma unroll
                for (int e = 0; e < 2; e++)
                    b[nt][e] = __float_as_uint(Bs[buf][bT0 + (nt * 2 + kb) * BT + e * BE + lane]);
#pragma unroll
            for (int mt = 0; mt < 4; mt++)
#pragma unroll
                for (int nt = 0; nt < 4; nt++)
                    mma_tf32(acc[mt][nt], a[mt], b[nt]);
        }
        if (ks + 2 < KSTAGES) {
#pragma unroll
            for (int i = 0; i < 2; i++) {
                pa[i] = Ap[i][(ks + 2) * 4];
                pb[i] = Bp[i][(ks + 2) * 4];
            }
        }
        __syncthreads();
    }

    const int g = lane >> 2, tig = lane & 3;
#pragma unroll
    for (int mt = 0; mt < 4; mt++) {
#pragma unroll
        for (int nt = 0; nt < 4; nt++) {
            int row = bm + wm * 64 + mt * 16 + g;
            int col = bn + wn * 32 + nt * 8 + tig * 2;
            float* c0;
            size_t rstride;
            if (mode == 0) {
                c0 = C + (size_t)row * DMODEL + col;
                rstride = DMODEL;
            } else {
                int b = row >> 11, s = row & (SEQ - 1);
                int h = col >> 7, hd = col & 127;
                c0 = C + (((size_t)(b * NHEADS + h)) * SEQ + s) * HDIM + hd;
                rstride = HDIM;
            }
            *(float2*)c0 = make_float2(acc[mt][nt][0], acc[mt][nt][1]);
            *(float2*)(c0 + 8 * rstride) = make_float2(acc[mt][nt][2], acc[mt][nt][3]);
        }
    }
}

// =================== Flash attention (causal, tf32 mma, fragment layouts) ===================
// Qf: a-frag vector layout, (mtg*16+kt)*132 + lane*4 + e        (8448 w)
// Kp: b-frag pair layout,   (ntg*16+kt)*66 + 2*(Lf^swz) + e     (8448 w)
// Vp: b-frag pair layout,   (ntg*8 +kt)*66 + 2*(Lf^swz) + e     (8448 w)
// Ps: raw scores 64x68                                           (4352 w)
// Pf: P a-frag layout,      (mtg*8+kt)*132 + 4*(Lf^swz) + e     (4224 w)
#define QTS 132
#define OFF_KP 8448
#define OFF_VP 16896
#define OFF_PS 25344
#define OFF_PF 29696
#define OFF_RM 33920
#define FLASH_SMEM_BYTES ((OFF_RM + 3*64) * 4)   // 136448 B

__global__ __launch_bounds__(256)
void flash_fwd(const float* __restrict__ Qg, const float* __restrict__ Kg,
               const float* __restrict__ Vg, float* __restrict__ Og)
{
    extern __shared__ float smf[];
    float* Qf = smf;
    float* Kp = smf + OFF_KP;
    float* Vp = smf + OFF_VP;
    float* Ps = smf + OFF_PS;
    float* Pf = smf + OFF_PF;
    float* rm = smf + OFF_RM;
    float* rl = rm + 64;
    float* ra = rl + 64;

    const int tid  = threadIdx.x;
    const int wid  = tid >> 5;
    const int lane = tid & 31;
    const int g4 = lane >> 2, tig = lane & 3;
    const int wm = wid >> 2;
    const int wn = wid & 3;
    const int laneSwz = lane ^ ((lane >> 3) & 3);    // consumer swizzle
    const int bx = blockIdx.x;
    const int bh = blockIdx.y;
    const int m0 = bx * 64;
    const size_t base = (size_t)bh * SEQ * HDIM;
    const float scale = 0.08838834764831845f;

    // ---- Q -> Qf (a-frag, tf32) ----
#pragma unroll
    for (int i = 0; i < 8; i++) {
        int row = i * 8 + wid;
        float4 v = *(const float4*)(Qg + base + (size_t)(m0 + row) * HDIM + lane * 4);
        v = tf32x4(v);
        int mt = row >> 4, g = row & 7, hi = (row >> 3) & 1;
        int kt = lane >> 1, kh = lane & 1;
        int w = (mt * 16 + kt) * QTS + 16 * g + (hi + 2 * kh);
        Qf[w + 0] = v.x; Qf[w + 4] = v.y; Qf[w + 8] = v.z; Qf[w + 12] = v.w;
    }
    if (tid < 64) { rm[tid] = -1e30f; rl[tid] = 0.f; }

    float o[2][4][4];
#pragma unroll
    for (int mt = 0; mt < 2; mt++)
#pragma unroll
        for (int nt = 0; nt < 4; nt++)
#pragma unroll
            for (int e = 0; e < 4; e++) o[mt][nt][e] = 0.f;

    const int ntiles = bx + 1;
    for (int t = 0; t < ntiles; t++) {
        const int n0 = t * 64;
        __syncthreads();

        // ---- K tile -> Kp, V tile -> Vp ----
#pragma unroll
        for (int i = 0; i < 8; i++) {
            int row = i * 8 + wid;
            {   // K: n = row (warp-uniform), k = 4*lane..+3
                float4 kv = tf32x4(*(const float4*)(Kg + base + (size_t)(n0 + row) * HDIM + lane * 4));
                int g = row & 7, ntg = row >> 3;
                int a = (g >> 1) & 3;
                int kt = lane >> 1, e = lane & 1;
                float kj[4] = {kv.x, kv.y, kv.z, kv.w};
                int wb = (ntg * 16 + kt) * 66 + e;
#pragma unroll
                for (int j = 0; j < 4; j++)
                    Kp[wb + 2 * (4 * g + (j ^ a))] = kj[j];
            }
            {   // V: k = row (warp-uniform), n = 4*lane..+3
                float4 vv = tf32x4(*(const float4*)(Vg + base + (size_t)(n0 + row) * HDIM + lane * 4));
                int kt = row >> 3, e = (row >> 2) & 1, tg = row & 3;
                float vj[4] = {vv.x, vv.y, vv.z, vv.w};
#pragma unroll
                for (int j = 0; j < 4; j++) {
                    int n = 4 * lane + j;
                    int g = n & 7, ntg = n >> 3;
                    int Lf = 4 * g + tg;
                    Vp[(ntg * 8 + kt) * 66 + 2 * (Lf ^ ((g >> 1) & 3)) + e] = vj[j];
                }
            }
        }
        __syncthreads();

        // ---- S = Q K^T : warp tile 32m x 16n ----
        float s[2][2][4];
#pragma unroll
        for (int mt = 0; mt < 2; mt++)
#pragma unroll
            for (int nt = 0; nt < 2; nt++)
#pragma unroll
                for (int e = 0; e < 4; e++) s[mt][nt][e] = 0.f;

#pragma unroll
        for (int kt = 0; kt < 16; kt++) {
            uint32_t a[2][4], b[2][2];
#pragma unroll
            for (int mt = 0; mt < 2; mt++)
                *(uint4*)a[mt] = *(const uint4*)&Qf[((wm * 2 + mt) * 16 + kt) * QTS + lane * 4];
#pragma unroll
            for (int nt = 0; nt < 2; nt++)
                *(uint2*)b[nt] = *(const uint2*)&Kp[((wn * 2 + nt) * 16 + kt) * 66 + 2 * laneSwz];
#pragma unroll
            for (int mt = 0; mt < 2; mt++)
#pragma unroll
                for (int nt = 0; nt < 2; nt++)
                    mma_tf32(s[mt][nt], a[mt], b[nt]);
        }

        // ---- scores -> Ps (scale + causal) ----
        const bool diag = (t == bx);
#pragma unroll
        for (int mt = 0; mt < 2; mt++) {
#pragma unroll
            for (int nt = 0; nt < 2; nt++) {
                int r0 = wm * 32 + mt * 16 + g4;
                int c0 = wn * 16 + nt * 8 + 2 * tig;
#pragma unroll
                for (int h = 0; h < 2; h++) {
                    int rr = r0 + h * 8;
                    float v0 = s[mt][nt][2 * h + 0] * scale;
                    float v1 = s[mt][nt][2 * h + 1] * scale;
                    if (diag) {
                        int grow = m0 + rr;
                        if (n0 + c0     > grow) v0 = -1e30f;
                        if (n0 + c0 + 1 > grow) v1 = -1e30f;
                    }
                    *(float2*)&Ps[rr * 68 + c0] = make_float2(v0, v1);
                }
            }
        }
        __syncthreads();

        // ---- online softmax; write exp(p) into Pf (a-frag layout) ----
        {
            int row = tid >> 2, q = tid & 3;
            const float* pr = Ps + row * 68 + q * 16;
            int mtg = row >> 4, g = row & 7, hi = (row >> 3) & 1;
            int aS = (g >> 1) & 3;
            float mo = rm[row];
            float mx = mo;
#pragma unroll
            for (int c = 0; c < 16; c++) mx = fmaxf(mx, pr[c]);
            mx = fmaxf(mx, __shfl_xor_sync(0xFFFFFFFFu, mx, 1));
            mx = fmaxf(mx, __shfl_xor_sync(0xFFFFFFFFu, mx, 2));
            float l = 0.f;
#pragma unroll
            for (int c = 0; c < 16; c++) {
                float p = __expf(pr[c] - mx);
                l += p;
                int col = q * 16 + c;
                int kt = col >> 3, tg = col & 3, kh = (col >> 2) & 1;
                int Lf = 4 * g + tg;
                Pf[(mtg * 8 + kt) * 132 + 4 * (Lf ^ aS) + hi + 2 * kh] = to_tf32(p);
            }
            l += __shfl_xor_sync(0xFFFFFFFFu, l, 1);
            l += __shfl_xor_sync(0xFFFFFFFFu, l, 2);
            if (q == 0) {
                float alpha = __expf(mo - mx);
                rl[row] = rl[row] * alpha + l;
                rm[row] = mx;
                ra[row] = alpha;
            }
        }
        __syncthreads();

        // ---- PV: O += P V (vectorized fragment loads) ----
        {
            int rb0 = wm * 32 + g4;
            float al[2][2];
#pragma unroll
            for (int mt = 0; mt < 2; mt++) {
                al[mt][0] = ra[rb0 + mt * 16];
                al[mt][1] = ra[rb0 + mt * 16 + 8];
            }
#pragma unroll
            for (int mt = 0; mt < 2; mt++)
#pragma unroll
                for (int nt = 0; nt < 4; nt++) {
                    o[mt][nt][0] *= al[mt][0]; o[mt][nt][1] *= al[mt][0];
                    o[mt][nt][2] *= al[mt][1]; o[mt][nt][3] *= al[mt][1];
                }
#pragma unroll
            for (int kt = 0; kt < 8; kt++) {
                uint32_t a[2][4], b[4][2];
#pragma unroll
                for (int mt = 0; mt < 2; mt++)
                    *(uint4*)a[mt] = *(const uint4*)&Pf[((wm * 2 + mt) * 8 + kt) * 132 + 4 * laneSwz];
#pragma unroll
                for (int nt = 0; nt < 4; nt++)
                    *(uint2*)b[nt] = *(const uint2*)&Vp[((wn * 4 + nt) * 8 + kt) * 66 + 2 * laneSwz];
#pragma unroll
                for (int mt = 0; mt < 2; mt++)
#pragma unroll
                    for (int nt = 0; nt < 4; nt++)
                        mma_tf32(o[mt][nt], a[mt], b[nt]);
            }
        }
    }

    // ---- epilogue ----
    const int b = bh >> 4, h = bh & 15;
#pragma unroll
    for (int mt = 0; mt < 2; mt++) {
        int rloc0 = wm * 32 + mt * 16 + g4;
#pragma unroll
        for (int hh = 0; hh < 2; hh++) {
            int rloc = rloc0 + hh * 8;
            float inv = 1.f / rl[rloc];
            int srow = m0 + rloc;
            float* op = Og + ((size_t)(b * SEQ + srow)) * DMODEL + h * HDIM;
#pragma unroll
            for (int nt = 0; nt < 4; nt++) {
                int col = wn * 32 + nt * 8 + 2 * tig;
                *(float2*)(op + col) = make_float2(o[mt][nt][2 * hh] * inv,
                                                   o[mt][nt][2 * hh + 1] * inv);
            }
        }
    }
}

// =================== launch ===================
extern "C" void kernel_launch(void* const* d_in, const int* in_sizes, int n_in,
                              void* d_out, int out_size)
{
    (void)in_sizes; (void)n_in; (void)out_size;
    const float* hidden = (const float*)d_in[0];
    const float* Wq = (const float*)d_in[3];
    const float* Wk = (const float*)d_in[4];
    const float* Wv = (const float*)d_in[5];
    const float* Wo = (const float*)d_in[6];
    float* out = (float*)d_out;

    float *q, *k, *v, *attn;
    cudaGetSymbolAddress((void**)&q,    g_q);
    cudaGetSymbolAddress((void**)&k,    g_k);
    cudaGetSymbolAddress((void**)&v,    g_v);
    cudaGetSymbolAddress((void**)&attn, g_attn);

    cudaFuncSetAttribute(flash_fwd, cudaFuncAttributeMaxDynamicSharedMemorySize,
                         FLASH_SMEM_BYTES);

    rope_cache_kernel<<<(SEQ * 64 + 255) / 256, 256>>>();

    // fused QKV projection: grid.z selects weight/output
    dim3 gQKV(DMODEL / 128, MROWS / 128, 3);
    tf32_gemm<<<gQKV, 256>>>(hidden, Wq, Wk, Wv, q, k, v, 1);

    rope_apply_kernel<<<(BH * SEQ * 64 + 255) / 256, 256>>>();

    flash_fwd<<<dim3(SEQ / 64, BH), 256, FLASH_SMEM_BYTES>>>(q, k, v, attn);

    dim3 gO(DMODEL / 128, MROWS / 128, 1);
    tf32_gemm<<<gO, 256>>>(attn, Wo, Wo, Wo, out, out, out, 0);
}

// round 9
// speedup vs baseline: 1.5270x; 1.2676x over previous
#include <cuda_runtime.h>
#include <math.h>
#include <stdint.h>

#define BSZ    2
#define SEQ    2048
#define DMODEL 2048
#define NHEADS 16
#define HDIM   128
#define BH     (BSZ*NHEADS)
#define MROWS  (BSZ*SEQ)

// ---- scratch ----
__device__ float g_q[BH*SEQ*HDIM];
__device__ float g_k[BH*SEQ*HDIM];
__device__ float g_v[BH*SEQ*HDIM];
__device__ float g_attn[MROWS*DMODEL];
__device__ float g_cos[SEQ*64];
__device__ float g_sin[SEQ*64];

__device__ __forceinline__ float to_tf32(float x) {
    float y;
    asm("cvt.rna.tf32.f32 %0, %1;" : "=f"(y) : "f"(x));
    return y;
}
__device__ __forceinline__ void mma_tf32(float* c, const uint32_t* a, const uint32_t* b) {
    asm volatile(
        "mma.sync.aligned.m16n8k8.row.col.f32.tf32.tf32.f32 "
        "{%0,%1,%2,%3}, {%4,%5,%6,%7}, {%8,%9}, {%0,%1,%2,%3};"
        : "+f"(c[0]), "+f"(c[1]), "+f"(c[2]), "+f"(c[3])
        : "r"(a[0]), "r"(a[1]), "r"(a[2]), "r"(a[3]), "r"(b[0]), "r"(b[1]));
}
__device__ __forceinline__ float4 tf32x4(float4 v) {
    v.x = to_tf32(v.x); v.y = to_tf32(v.y); v.z = to_tf32(v.z); v.w = to_tf32(v.w);
    return v;
}

// =================== RoPE ===================
__global__ void rope_cache_kernel() {
    int idx = blockIdx.x * blockDim.x + threadIdx.x;
    if (idx >= SEQ * 64) return;
    int pos = idx >> 6, j = idx & 63;
    double e    = (double)(2 * j) / 128.0;
    double invf = pow(10000.0, -e);
    double ang  = (double)pos * invf;
    g_cos[idx] = (float)cos(ang);
    g_sin[idx] = (float)sin(ang);
}
__global__ void rope_apply_kernel() {
    int idx = blockIdx.x * blockDim.x + threadIdx.x;
    if (idx >= BH * SEQ * 64) return;
    int j = idx & 63, row = idx >> 6, s = row & (SEQ - 1);
    float c = g_cos[s * 64 + j], sn = g_sin[s * 64 + j];
    float* qp = g_q + (size_t)row * HDIM;
    float* kp = g_k + (size_t)row * HDIM;
    float q1 = qp[j], q2 = qp[j + 64];
    qp[j] = q1 * c - q2 * sn;  qp[j + 64] = q2 * c + q1 * sn;
    float k1 = kp[j], k2 = kp[j + 64];
    kp[j] = k1 * c - k2 * sn;  kp[j + 64] = k2 * c + k1 * sn;
}

// =================== TF32 GEMM (R3 design: e-plane, double-buffered, 8 warps) ===================
#define GEMM_K  DMODEL
#define KSTAGES (GEMM_K / 16)    // 128
#define AE 36
#define AT 144
#define BE 40
#define BT 80
#define A_STAGE (16*AT)
#define B_STAGE (32*BT)

__global__ __launch_bounds__(256, 2)
void tf32_gemm(const float* __restrict__ A,
               const float* __restrict__ B0, const float* __restrict__ B1,
               const float* __restrict__ B2,
               float* __restrict__ C0, float* __restrict__ C1, float* __restrict__ C2,
               int mode)
{
    __shared__ float As[2][A_STAGE];
    __shared__ float Bs[2][B_STAGE];

    const int z = blockIdx.z;
    const float* B = (z == 0) ? B0 : (z == 1) ? B1 : B2;
    float* C       = (z == 0) ? C0 : (z == 1) ? C1 : C2;

    const int tid  = threadIdx.x;
    const int wid  = tid >> 5;
    const int lane = tid & 31;
    const int bm = blockIdx.y * 128;
    const int bn = blockIdx.x * 128;
    const int wm = wid >> 2;
    const int wn = wid & 3;

    int aWord[2], bWord[2];
    const float4* Ap[2];
    const float4* Bp[2];
#pragma unroll
    for (int i = 0; i < 2; i++) {
        int f = i * 256 + tid;
        int row = f >> 2, c4 = f & 3;
        int kb = c4 >> 1, kh = c4 & 1;
        int g = row & 7, hi = (row >> 3) & 1;
        int mt = row >> 4, nt = row >> 3;
        aWord[i] = (mt * 2 + kb) * AT + (hi + 2 * kh) * AE + g * 4;
        bWord[i] = (nt * 2 + kb) * BT + kh * BE + g * 4;
        Ap[i] = (const float4*)(A + (size_t)(bm + row) * GEMM_K) + c4;
        Bp[i] = (const float4*)(B + (size_t)(bn + row) * GEMM_K) + c4;
    }

    float acc[4][4][4];
#pragma unroll
    for (int mt = 0; mt < 4; mt++)
#pragma unroll
        for (int nt = 0; nt < 4; nt++)
#pragma unroll
            for (int e = 0; e < 4; e++) acc[mt][nt][e] = 0.f;

    float4 pa[2], pb[2];
#pragma unroll
    for (int i = 0; i < 2; i++) { pa[i] = Ap[i][0]; pb[i] = Bp[i][0]; }
#pragma unroll
    for (int i = 0; i < 2; i++) {
        *(float4*)&As[0][aWord[i]] = tf32x4(pa[i]);
        *(float4*)&Bs[0][bWord[i]] = tf32x4(pb[i]);
    }
#pragma unroll
    for (int i = 0; i < 2; i++) { pa[i] = Ap[i][4]; pb[i] = Bp[i][4]; }
    __syncthreads();

    const int aT0 = (wm * 4) * 2 * AT;
    const int bT0 = (wn * 4) * 2 * BT;

#pragma unroll 1
    for (int ks = 0; ks < KSTAGES; ks++) {
        const int buf = ks & 1;
        if (ks + 1 < KSTAGES) {
#pragma unroll
            for (int i = 0; i < 2; i++) {
                *(float4*)&As[buf ^ 1][aWord[i]] = tf32x4(pa[i]);
                *(float4*)&Bs[buf ^ 1][bWord[i]] = tf32x4(pb[i]);
            }
        }
#pragma unroll
        for (int kb = 0; kb < 2; kb++) {
            uint32_t a[4][4], b[4][2];
#pragma unroll
            for (int mt = 0; mt < 4; mt++)
#pragma unroll
                for (int e = 0; e < 4; e++)
                    a[mt][e] = __float_as_uint(As[buf][aT0 + (mt * 2 + kb) * AT + e * AE + lane]);
#pragma unroll
            for (int nt = 0; nt < 4; nt++)
#pragma unroll
                for (int e = 0; e < 2; e++)
                    b[nt][e] = __float_as_uint(Bs[buf][bT0 + (nt * 2 + kb) * BT + e * BE + lane]);
#pragma unroll
            for (int mt = 0; mt < 4; mt++)
#pragma unroll
                for (int nt = 0; nt < 4; nt++)
                    mma_tf32(acc[mt][nt], a[mt], b[nt]);
        }
        if (ks + 2 < KSTAGES) {
#pragma unroll
            for (int i = 0; i < 2; i++) {
                pa[i] = Ap[i][(ks + 2) * 4];
                pb[i] = Bp[i][(ks + 2) * 4];
            }
        }
        __syncthreads();
    }

    const int g = lane >> 2, tig = lane & 3;
#pragma unroll
    for (int mt = 0; mt < 4; mt++) {
#pragma unroll
        for (int nt = 0; nt < 4; nt++) {
            int row = bm + wm * 64 + mt * 16 + g;
            int col = bn + wn * 32 + nt * 8 + tig * 2;
            float* c0;
            size_t rstride;
            if (mode == 0) {
                c0 = C + (size_t)row * DMODEL + col;
                rstride = DMODEL;
            } else {
                int b = row >> 11, s = row & (SEQ - 1);
                int h = col >> 7, hd = col & 127;
                c0 = C + (((size_t)(b * NHEADS + h)) * SEQ + s) * HDIM + hd;
                rstride = HDIM;
            }
            *(float2*)c0 = make_float2(acc[mt][nt][0], acc[mt][nt][1]);
            *(float2*)(c0 + 8 * rstride) = make_float2(acc[mt][nt][2], acc[mt][nt][3]);
        }
    }
}

// =================== Flash attention (register-resident P, permuted K, TRUE-ordered V) ===================
// 128 q-rows/CTA, 8 warps x 16 rows, Q in registers, K/V only in smem.
// K b-frag e-plane, n-position permuted by pi(j)= j<4 ? 2j : 2(j-4)+1:
//   Kf[(ntg*16+kt)*72 + kh*36 + pi(n&7)*4 + j]
// V b-frag e-plane, k (kv) position in TRUE order (b0 slot must be true kv=tig):
//   Vf[(n>>3)*577 + ktv*72 + ((kv&7)>>2)*36 + (n&7)*4 + (kv&3)]
// With pi on K only, the QK^T accumulator in TRUE kv ordering is
//   s0=S[r][tig], s1=S[r][tig+4], s2=S[r+8][tig], s3=S[r+8][tig+4],
// so the PV A-fragment is exactly a = {s0, s2, s1, s3}.
#define FKTS 72
#define FKE  36
#define FVTS 577
#define FOFF_V 9216
#define FLASH_SMEM_BYTES ((9216 + 9248) * 4)   // 73856 B

__global__ __launch_bounds__(256, 1)
void flash_fwd(const float* __restrict__ Qg, const float* __restrict__ Kg,
               const float* __restrict__ Vg, float* __restrict__ Og)
{
    extern __shared__ float smf[];
    float* Kf = smf;
    float* Vf = smf + FOFF_V;

    const int tid  = threadIdx.x;
    const int wid  = tid >> 5;
    const int lane = tid & 31;
    const int g4 = lane >> 2, tig = lane & 3;
    const int qt = (int)(gridDim.x - 1 - blockIdx.x);   // heavy CTAs first
    const int bh = blockIdx.y;
    const int m0 = qt * 128;
    const int warpRow = m0 + wid * 16;
    const size_t base = (size_t)bh * SEQ * HDIM;
    const float scale = 0.08838834764831845f;

    // ---- Q a-fragments in registers (scale folded in) ----
    uint32_t qa[16][4];
    {
        const float* qA = Qg + base + (size_t)(warpRow + g4) * HDIM;
        const float* qB = qA + 8 * HDIM;
#pragma unroll
        for (int kt = 0; kt < 16; kt++) {
            qa[kt][0] = __float_as_uint(to_tf32(qA[kt * 8 + tig] * scale));
            qa[kt][1] = __float_as_uint(to_tf32(qB[kt * 8 + tig] * scale));
            qa[kt][2] = __float_as_uint(to_tf32(qA[kt * 8 + tig + 4] * scale));
            qa[kt][3] = __float_as_uint(to_tf32(qB[kt * 8 + tig + 4] * scale));
        }
    }

    float o[16][4];
#pragma unroll
    for (int nt = 0; nt < 16; nt++)
#pragma unroll
        for (int e = 0; e < 4; e++) o[nt][e] = 0.f;
    float mA = -1e30f, mB = -1e30f, lA = 0.f, lB = 0.f;

    const int ntiles = 2 * qt + 2;
    for (int t = 0; t < ntiles; t++) {
        const int n0 = t * 64;
        __syncthreads();

        // ---- fill K (permuted n) and V (true k order) ----
#pragma unroll
        for (int i = 0; i < 8; i++) {
            int row = i * 8 + wid;          // warp-uniform kv row 0..63
            int gt = row & 7;
            int gp = (gt < 4) ? 2 * gt : 2 * (gt - 4) + 1;   // pi(gt), K only
            {
                float4 kv = tf32x4(*(const float4*)(Kg + base + (size_t)(n0 + row) * HDIM + lane * 4));
                int ntg = row >> 3, kt = lane >> 1, kh = lane & 1;
                *(float4*)&Kf[(ntg * 16 + kt) * FKTS + kh * FKE + gp * 4] = kv;
            }
            {
                float4 vv = tf32x4(*(const float4*)(Vg + base + (size_t)(n0 + row) * HDIM + lane * 4));
                int ktv = row >> 3, ev = gt >> 2, q4 = gt & 3;   // TRUE kv position
                float vj[4] = {vv.x, vv.y, vv.z, vv.w};
#pragma unroll
                for (int j = 0; j < 4; j++) {
                    int n = 4 * lane + j;
                    Vf[(n >> 3) * FVTS + ktv * FKTS + ev * FKE + (n & 7) * 4 + q4] = vj[j];
                }
            }
        }
        __syncthreads();

        // warp-level skip: tile entirely above this warp's rows
        if (n0 > warpRow + 15) continue;

        // ---- S = Q K^T ----
        float s[8][4];
#pragma unroll
        for (int nt = 0; nt < 8; nt++)
#pragma unroll
            for (int e = 0; e < 4; e++) s[nt][e] = 0.f;
#pragma unroll
        for (int kt = 0; kt < 16; kt++) {
            uint32_t b[8][2];
#pragma unroll
            for (int nt = 0; nt < 8; nt++) {
                b[nt][0] = __float_as_uint(Kf[(nt * 16 + kt) * FKTS + lane]);
                b[nt][1] = __float_as_uint(Kf[(nt * 16 + kt) * FKTS + FKE + lane]);
            }
#pragma unroll
            for (int nt = 0; nt < 8; nt++)
                mma_tf32(s[nt], qa[kt], b[nt]);
        }

        // ---- causal mask (accumulator cols are TRUE kv: tig / tig+4) ----
        const int qrA = warpRow + g4, qrB = qrA + 8;
        if (n0 + 63 > warpRow) {
#pragma unroll
            for (int nt = 0; nt < 8; nt++) {
                int kv0 = n0 + nt * 8 + tig, kv1 = kv0 + 4;
                if (kv0 > qrA) s[nt][0] = -1e30f;
                if (kv1 > qrA) s[nt][1] = -1e30f;
                if (kv0 > qrB) s[nt][2] = -1e30f;
                if (kv1 > qrB) s[nt][3] = -1e30f;
            }
        }

        // ---- online softmax (registers + quad shuffles) ----
        float mxA = -1e30f, mxB = -1e30f;
#pragma unroll
        for (int nt = 0; nt < 8; nt++) {
            mxA = fmaxf(mxA, fmaxf(s[nt][0], s[nt][1]));
            mxB = fmaxf(mxB, fmaxf(s[nt][2], s[nt][3]));
        }
        mxA = fmaxf(mxA, __shfl_xor_sync(0xFFFFFFFFu, mxA, 1));
        mxA = fmaxf(mxA, __shfl_xor_sync(0xFFFFFFFFu, mxA, 2));
        mxB = fmaxf(mxB, __shfl_xor_sync(0xFFFFFFFFu, mxB, 1));
        mxB = fmaxf(mxB, __shfl_xor_sync(0xFFFFFFFFu, mxB, 2));
        float mnA = fmaxf(mA, mxA), mnB = fmaxf(mB, mxB);
        float aAl = __expf(mA - mnA), aBl = __expf(mB - mnB);
        mA = mnA; mB = mnB;
#pragma unroll
        for (int nt = 0; nt < 16; nt++) {
            o[nt][0] *= aAl; o[nt][1] *= aAl;
            o[nt][2] *= aBl; o[nt][3] *= aBl;
        }
        float sumA = 0.f, sumB = 0.f;
#pragma unroll
        for (int nt = 0; nt < 8; nt++) {
            float p0 = to_tf32(__expf(s[nt][0] - mA));
            float p1 = to_tf32(__expf(s[nt][1] - mA));
            float p2 = to_tf32(__expf(s[nt][2] - mB));
            float p3 = to_tf32(__expf(s[nt][3] - mB));
            s[nt][0] = p0; s[nt][1] = p1; s[nt][2] = p2; s[nt][3] = p3;
            sumA += p0 + p1; sumB += p2 + p3;
        }
        lA = lA * aAl + sumA;
        lB = lB * aBl + sumB;

        // ---- O += P V  (P a-frag = {s0, s2, s1, s3}) ----
#pragma unroll
        for (int kp = 0; kp < 8; kp++) {
            uint32_t a[4] = { __float_as_uint(s[kp][0]), __float_as_uint(s[kp][2]),
                              __float_as_uint(s[kp][1]), __float_as_uint(s[kp][3]) };
            uint32_t b[16][2];
#pragma unroll
            for (int nt = 0; nt < 16; nt++) {
                b[nt][0] = __float_as_uint(Vf[nt * FVTS + kp * FKTS + lane]);
                b[nt][1] = __float_as_uint(Vf[nt * FVTS + kp * FKTS + FKE + lane]);
            }
#pragma unroll
            for (int nt = 0; nt < 16; nt++)
                mma_tf32(o[nt], a, b[nt]);
        }
    }

    // ---- epilogue ----
    lA += __shfl_xor_sync(0xFFFFFFFFu, lA, 1);
    lA += __shfl_xor_sync(0xFFFFFFFFu, lA, 2);
    lB += __shfl_xor_sync(0xFFFFFFFFu, lB, 1);
    lB += __shfl_xor_sync(0xFFFFFFFFu, lB, 2);
    float invA = 1.f / lA, invB = 1.f / lB;
    const int b_ = bh >> 4, h = bh & 15;
    const int srA = warpRow + g4, srB = srA + 8;
    float* opA = Og + ((size_t)(b_ * SEQ + srA)) * DMODEL + h * HDIM;
    float* opB = Og + ((size_t)(b_ * SEQ + srB)) * DMODEL + h * HDIM;
#pragma unroll
    for (int nt = 0; nt < 16; nt++) {
        *(float2*)(opA + nt * 8 + 2 * tig) = make_float2(o[nt][0] * invA, o[nt][1] * invA);
        *(float2*)(opB + nt * 8 + 2 * tig) = make_float2(o[nt][2] * invB, o[nt][3] * invB);
    }
}

// =================== launch ===================
extern "C" void kernel_launch(void* const* d_in, const int* in_sizes, int n_in,
                              void* d_out, int out_size)
{
    (void)in_sizes; (void)n_in; (void)out_size;
    const float* hidden = (const float*)d_in[0];
    const float* Wq = (const float*)d_in[3];
    const float* Wk = (const float*)d_in[4];
    const float* Wv = (const float*)d_in[5];
    const float* Wo = (const float*)d_in[6];
    float* out = (float*)d_out;

    float *q, *k, *v, *attn;
    cudaGetSymbolAddress((void**)&q,    g_q);
    cudaGetSymbolAddress((void**)&k,    g_k);
    cudaGetSymbolAddress((void**)&v,    g_v);
    cudaGetSymbolAddress((void**)&attn, g_attn);

    cudaFuncSetAttribute(flash_fwd, cudaFuncAttributeMaxDynamicSharedMemorySize,
                         FLASH_SMEM_BYTES);

    rope_cache_kernel<<<(SEQ * 64 + 255) / 256, 256>>>();

    dim3 gQKV(DMODEL / 128, MROWS / 128, 3);
    tf32_gemm<<<gQKV, 256>>>(hidden, Wq, Wk, Wv, q, k, v, 1);

    rope_apply_kernel<<<(BH * SEQ * 64 + 255) / 256, 256>>>();

    flash_fwd<<<dim3(SEQ / 128, BH), 256, FLASH_SMEM_BYTES>>>(q, k, v, attn);

    dim3 gO(DMODEL / 128, MROWS / 128, 1);
    tf32_gemm<<<gO, 256>>>(attn, Wo, Wo, Wo, out, out, out, 0);
}